// round 4
// baseline (speedup 1.0000x reference)
#include <cuda_runtime.h>
#include <cstdint>

#define BB 32
#define NN 4096
#define CC 1024
#define HH 16
#define HD 16
#define CR 256
#define SCALE 0.25f

// ---------------- scratch (device globals; no allocations allowed) ----------------
__device__ float g_wqT[(size_t)BB * CC * HH];     // [b][c][h]   2 MB
__device__ float g_logitsT[(size_t)BB * NN * HH]; // [b][n][h]   8 MB
__device__ float g_attnT[(size_t)BB * NN * HH];   // [b][n][h]   8 MB
__device__ float g_s[(size_t)BB * HH * CC];       // [b][h][c]   2 MB

// ---------------- kernel A: q = x[:,0]@Wq*SCALE ; wqT[b][c][h] = sum_d q[h,d]*Wk[c, h*16+d]
__global__ void kA(const float* __restrict__ x, const float* __restrict__ Wq,
                   const float* __restrict__ Wk) {
    int b = blockIdx.x, tid = threadIdx.x;
    __shared__ float x0[CC];
    __shared__ float qs[CR];
    for (int c = tid; c < CC; c += 256) x0[c] = x[(size_t)b * NN * CC + c];
    __syncthreads();
    // q[j], j = tid (h = j/16, d = j%16)
    float acc = 0.f;
    for (int c = 0; c < CC; ++c) acc += x0[c] * Wq[(size_t)c * CR + tid];
    qs[tid] = acc * SCALE;
    __syncthreads();
    for (int idx = tid; idx < CC * HH; idx += 256) {
        int c = idx >> 4, h = idx & 15;
        const float* wk = Wk + (size_t)c * CR + h * HD;
        const float* qq = qs + h * HD;
        float a = 0.f;
#pragma unroll
        for (int d = 0; d < HD; ++d) a += qq[d] * wk[d];
        g_wqT[((size_t)b * CC + c) * HH + h] = a;
    }
}

// ---------------- kernel B: logitsT[b][n][h] = sum_c x[b][n][c] * wqT[b][c][h]
// grid (N/256, B), block 256. Thread owns one token, 16 head accumulators.
__global__ void kB(const float* __restrict__ x) {
    int b = blockIdx.y, n0 = blockIdx.x * 256, tid = threadIdx.x;
    __shared__ float xs[32][257];       // transposed k-tile [c][n], pad for banks
    __shared__ float4 wqs[32 * 4];      // [cc][4] -> 16 head values
    float acc[16];
#pragma unroll
    for (int h = 0; h < 16; ++h) acc[h] = 0.f;

    const float* xb = x + ((size_t)b * NN + n0) * CC;
    const float* wb = g_wqT + (size_t)b * CC * HH;

    for (int k0 = 0; k0 < CC; k0 += 32) {
        // load x tile: 256 tokens x 32 channels, transposed into smem
#pragma unroll
        for (int i = 0; i < 8; ++i) {
            int n = (tid >> 3) + i * 32;
            int cg = (tid & 7) * 4;
            float4 v = *(const float4*)(xb + (size_t)n * CC + k0 + cg);
            xs[cg + 0][n] = v.x;
            xs[cg + 1][n] = v.y;
            xs[cg + 2][n] = v.z;
            xs[cg + 3][n] = v.w;
        }
        // load wq tile: 32 c x 16 h = 128 float4
        if (tid < 128) {
            wqs[tid] = *(const float4*)(wb + (size_t)(k0 + (tid >> 2)) * HH + (tid & 3) * 4);
        }
        __syncthreads();
#pragma unroll
        for (int cc = 0; cc < 32; ++cc) {
            float xv = xs[cc][tid];
            float4 w0 = wqs[4 * cc + 0], w1 = wqs[4 * cc + 1];
            float4 w2 = wqs[4 * cc + 2], w3 = wqs[4 * cc + 3];
            acc[0]  += xv * w0.x; acc[1]  += xv * w0.y; acc[2]  += xv * w0.z; acc[3]  += xv * w0.w;
            acc[4]  += xv * w1.x; acc[5]  += xv * w1.y; acc[6]  += xv * w1.z; acc[7]  += xv * w1.w;
            acc[8]  += xv * w2.x; acc[9]  += xv * w2.y; acc[10] += xv * w2.z; acc[11] += xv * w2.w;
            acc[12] += xv * w3.x; acc[13] += xv * w3.y; acc[14] += xv * w3.z; acc[15] += xv * w3.w;
        }
        __syncthreads();
    }
    float4* out = (float4*)(g_logitsT + ((size_t)b * NN + n0 + tid) * HH);
    out[0] = make_float4(acc[0], acc[1], acc[2], acc[3]);
    out[1] = make_float4(acc[4], acc[5], acc[6], acc[7]);
    out[2] = make_float4(acc[8], acc[9], acc[10], acc[11]);
    out[3] = make_float4(acc[12], acc[13], acc[14], acc[15]);
}

// ---------------- kernel C: softmax over n for each (b,h)
__global__ void kC() {
    int b = blockIdx.x, tid = threadIdx.x;
    const float* L = g_logitsT + (size_t)b * NN * HH;
    float* A = g_attnT + (size_t)b * NN * HH;
    __shared__ float red[256][17];

    float m[16];
#pragma unroll
    for (int h = 0; h < 16; ++h) m[h] = -1e30f;
    for (int n = tid; n < NN; n += 256) {
        const float4* l4 = (const float4*)(L + (size_t)n * HH);
        float4 v0 = l4[0], v1 = l4[1], v2 = l4[2], v3 = l4[3];
        m[0] = fmaxf(m[0], v0.x); m[1] = fmaxf(m[1], v0.y); m[2] = fmaxf(m[2], v0.z); m[3] = fmaxf(m[3], v0.w);
        m[4] = fmaxf(m[4], v1.x); m[5] = fmaxf(m[5], v1.y); m[6] = fmaxf(m[6], v1.z); m[7] = fmaxf(m[7], v1.w);
        m[8] = fmaxf(m[8], v2.x); m[9] = fmaxf(m[9], v2.y); m[10] = fmaxf(m[10], v2.z); m[11] = fmaxf(m[11], v2.w);
        m[12] = fmaxf(m[12], v3.x); m[13] = fmaxf(m[13], v3.y); m[14] = fmaxf(m[14], v3.z); m[15] = fmaxf(m[15], v3.w);
    }
#pragma unroll
    for (int h = 0; h < 16; ++h) red[tid][h] = m[h];
    __syncthreads();
    for (int s = 128; s > 0; s >>= 1) {
        if (tid < s) {
#pragma unroll
            for (int h = 0; h < 16; ++h) red[tid][h] = fmaxf(red[tid][h], red[tid + s][h]);
        }
        __syncthreads();
    }
#pragma unroll
    for (int h = 0; h < 16; ++h) m[h] = red[0][h];
    __syncthreads();

    float sm[16];
#pragma unroll
    for (int h = 0; h < 16; ++h) sm[h] = 0.f;
    for (int n = tid; n < NN; n += 256) {
        const float* l = L + (size_t)n * HH;
#pragma unroll
        for (int h = 0; h < 16; ++h) sm[h] += __expf(l[h] - m[h]);
    }
#pragma unroll
    for (int h = 0; h < 16; ++h) red[tid][h] = sm[h];
    __syncthreads();
    for (int s = 128; s > 0; s >>= 1) {
        if (tid < s) {
#pragma unroll
            for (int h = 0; h < 16; ++h) red[tid][h] += red[tid + s][h];
        }
        __syncthreads();
    }
    float inv[16];
#pragma unroll
    for (int h = 0; h < 16; ++h) inv[h] = 1.f / red[0][h];

    for (int n = tid; n < NN; n += 256) {
        const float* l = L + (size_t)n * HH;
        float4* a4 = (float4*)(A + (size_t)n * HH);
        float r[16];
#pragma unroll
        for (int h = 0; h < 16; ++h) r[h] = __expf(l[h] - m[h]) * inv[h];
        a4[0] = make_float4(r[0], r[1], r[2], r[3]);
        a4[1] = make_float4(r[4], r[5], r[6], r[7]);
        a4[2] = make_float4(r[8], r[9], r[10], r[11]);
        a4[3] = make_float4(r[12], r[13], r[14], r[15]);
    }
}

// ---------------- kernel D: g_s[b][h][c] = sum_n attnT[b][n][h] * x[b][n][c]
// grid (4 c-tiles, B) = 128 CTAs, block 256. Thread owns 1 channel x 16 heads.
// Internal loop over 8 n-chunks of 512; attn tile staged in smem per chunk.
// No atomics -> fully deterministic.
__global__ void kD(const float* __restrict__ x) {
    int b = blockIdx.y, ct = blockIdx.x, tid = threadIdx.x;
    int c0 = ct * 256 + tid;
    __shared__ float4 ats[512 * 4];  // attn tile [n][4xfloat4] = 32KB

    float acc[16];
#pragma unroll
    for (int i = 0; i < 16; ++i) acc[i] = 0.f;

    for (int nch = 0; nch < 8; ++nch) {
        int n1 = nch * 512;
        const float4* asrc = (const float4*)(g_attnT + ((size_t)b * NN + n1) * HH);
#pragma unroll
        for (int i = 0; i < 8; ++i) ats[tid + i * 256] = asrc[tid + i * 256];
        __syncthreads();

        const float* xb = x + ((size_t)b * NN + n1) * CC + c0;
#pragma unroll 8
        for (int n = 0; n < 512; ++n) {
            float xv = xb[(size_t)n * CC];
            float4 a0 = ats[4 * n + 0], a1 = ats[4 * n + 1];
            float4 a2 = ats[4 * n + 2], a3 = ats[4 * n + 3];
            acc[0]  += xv * a0.x; acc[1]  += xv * a0.y;
            acc[2]  += xv * a0.z; acc[3]  += xv * a0.w;
            acc[4]  += xv * a1.x; acc[5]  += xv * a1.y;
            acc[6]  += xv * a1.z; acc[7]  += xv * a1.w;
            acc[8]  += xv * a2.x; acc[9]  += xv * a2.y;
            acc[10] += xv * a2.z; acc[11] += xv * a2.w;
            acc[12] += xv * a3.x; acc[13] += xv * a3.y;
            acc[14] += xv * a3.z; acc[15] += xv * a3.w;
        }
        __syncthreads();
    }
#pragma unroll
    for (int h = 0; h < 16; ++h) {
        g_s[((size_t)b * HH + h) * CC + c0] = acc[h];
    }
}

// ---------------- kernel E: o[j] = sum_c s[b][j/16][c]*Wv[c][j]; out = o@Wp + bp
__global__ void kE(const float* __restrict__ Wv, const float* __restrict__ Wp,
                   const float* __restrict__ bp, float* __restrict__ out) {
    int b = blockIdx.x, tid = threadIdx.x;
    __shared__ float o_s[CR];
    const float* sb = g_s + ((size_t)b * HH + (tid >> 4)) * CC;
    float a = 0.f;
    for (int c = 0; c < CC; ++c) a += sb[c] * Wv[(size_t)c * CR + tid];
    o_s[tid] = a;
    __syncthreads();
#pragma unroll
    for (int i = 0; i < 4; ++i) {
        int j = tid + i * 256;
        float r = bp[j];
        for (int c2 = 0; c2 < CR; ++c2) r += o_s[c2] * Wp[(size_t)c2 * CC + j];
        out[(size_t)b * CC + j] = r;
    }
}

extern "C" void kernel_launch(void* const* d_in, const int* in_sizes, int n_in,
                              void* d_out, int out_size) {
    const float* x  = (const float*)d_in[0];
    const float* Wq = (const float*)d_in[1];
    const float* Wk = (const float*)d_in[2];
    const float* Wv = (const float*)d_in[3];
    const float* Wp = (const float*)d_in[4];
    const float* bp = (const float*)d_in[5];
    float* out = (float*)d_out;

    kA<<<BB, 256>>>(x, Wq, Wk);
    kB<<<dim3(NN / 256, BB), 256>>>(x);
    kC<<<BB, 256>>>();
    kD<<<dim3(4, BB), 256>>>(x);
    kE<<<BB, 256>>>(Wv, Wp, bp, out);
}

// round 5
// speedup vs baseline: 1.6342x; 1.6342x over previous
#include <cuda_runtime.h>
#include <cstdint>

typedef unsigned long long u64;

#define BB 32
#define NN 4096
#define CC 1024
#define HH 16
#define HD 16
#define CR 256
#define SCALE 0.25f
#define NSTRIP 8
#define STRIP 512

// ---------------- scratch (device globals; no allocations allowed) ----------------
__device__ float g_wqT[(size_t)BB * CC * HH];        // [b][c][h]        2 MB
__device__ float g_logitsT[(size_t)BB * NN * HH];    // [b][n][h]        8 MB
__device__ float g_attnT[(size_t)BB * NN * HH];      // exp(l - m_strip) 8 MB
__device__ float g_smax[BB * NSTRIP * HH];
__device__ float g_ssum[BB * NSTRIP * HH];
__device__ float g_f[BB * NSTRIP * HH];              // exp(m_s - M)/S
__device__ float g_part[(size_t)BB * NSTRIP * HH * CC]; // 16 MB split-K partials
__device__ float g_s[(size_t)BB * HH * CC];          // [b][h][c]        2 MB

// ---------------- packed fp32x2 helpers ----------------
__device__ __forceinline__ u64 dup2(float x) {
    u64 d; unsigned u = __float_as_uint(x);
    asm("mov.b64 %0, {%1, %1};" : "=l"(d) : "r"(u));
    return d;
}
__device__ __forceinline__ void fma2(u64& d, u64 a, u64 b) {
    asm("fma.rn.f32x2 %0, %1, %2, %0;" : "+l"(d) : "l"(a), "l"(b));
}

// ---------------- kernel A: q = x[:,0]@Wq*SCALE ; wqT[b][c][h] = sum_d q[h,d]*Wk[c,h*16+d]
__global__ void kA(const float* __restrict__ x, const float* __restrict__ Wq,
                   const float* __restrict__ Wk) {
    int b = blockIdx.x, tid = threadIdx.x;
    __shared__ float x0[CC];
    __shared__ float qs[CR];
    for (int c = tid; c < CC; c += 256) x0[c] = x[(size_t)b * NN * CC + c];
    __syncthreads();
    float acc = 0.f;
    for (int c = 0; c < CC; ++c) acc += x0[c] * Wq[(size_t)c * CR + tid];
    qs[tid] = acc * SCALE;
    __syncthreads();
    for (int idx = tid; idx < CC * HH; idx += 256) {
        int c = idx >> 4, h = idx & 15;
        const float* wk = Wk + (size_t)c * CR + h * HD;
        const float* qq = qs + h * HD;
        float a = 0.f;
#pragma unroll
        for (int d = 0; d < HD; ++d) a += qq[d] * wk[d];
        g_wqT[((size_t)b * CC + c) * HH + h] = a;
    }
}

// ---------------- kernel B: logitsT[b][n][h] = sum_c x[b][n][c] * wqT[b][c][h]
// grid (N/256, B), block 256. Thread owns one token, 8 packed-pair accumulators.
__global__ void kB(const float* __restrict__ x) {
    int b = blockIdx.y, n0 = blockIdx.x * 256, tid = threadIdx.x;
    __shared__ float xs[32][257];       // transposed k-tile [c][n]
    __shared__ float4 wqs[32 * 4];      // [cc][4] -> 16 head values
    u64 acc[8];
#pragma unroll
    for (int j = 0; j < 8; ++j) acc[j] = 0ull;

    const float* xb = x + ((size_t)b * NN + n0) * CC;
    const float* wb = g_wqT + (size_t)b * CC * HH;

    for (int k0 = 0; k0 < CC; k0 += 32) {
#pragma unroll
        for (int i = 0; i < 8; ++i) {
            int n = (tid >> 3) + i * 32;
            int cg = (tid & 7) * 4;
            float4 v = *(const float4*)(xb + (size_t)n * CC + k0 + cg);
            xs[cg + 0][n] = v.x;
            xs[cg + 1][n] = v.y;
            xs[cg + 2][n] = v.z;
            xs[cg + 3][n] = v.w;
        }
        if (tid < 128) {
            wqs[tid] = *(const float4*)(wb + (size_t)(k0 + (tid >> 2)) * HH + (tid & 3) * 4);
        }
        __syncthreads();
        const u64* wu = (const u64*)wqs;
#pragma unroll
        for (int cc = 0; cc < 32; ++cc) {
            u64 xd = dup2(xs[cc][tid]);
            fma2(acc[0], xd, wu[cc * 8 + 0]);
            fma2(acc[1], xd, wu[cc * 8 + 1]);
            fma2(acc[2], xd, wu[cc * 8 + 2]);
            fma2(acc[3], xd, wu[cc * 8 + 3]);
            fma2(acc[4], xd, wu[cc * 8 + 4]);
            fma2(acc[5], xd, wu[cc * 8 + 5]);
            fma2(acc[6], xd, wu[cc * 8 + 6]);
            fma2(acc[7], xd, wu[cc * 8 + 7]);
        }
        __syncthreads();
    }
    u64* out = (u64*)(g_logitsT + ((size_t)b * NN + n0 + tid) * HH);
#pragma unroll
    for (int j = 0; j < 8; ++j) out[j] = acc[j];
}

// ---------------- kernel Ca: per-strip softmax stats + exp store
// grid (NSTRIP, B), block 256. Each thread handles 2 tokens of the 512-strip.
__global__ void kCa() {
    int s = blockIdx.x, b = blockIdx.y, tid = threadIdx.x;
    const float* L = g_logitsT + ((size_t)b * NN + s * STRIP) * HH;
    float* A = g_attnT + ((size_t)b * NN + s * STRIP) * HH;
    __shared__ float red[256][17];

    float m[16];
#pragma unroll
    for (int h = 0; h < 16; ++h) m[h] = -1e30f;
#pragma unroll
    for (int i = 0; i < 2; ++i) {
        int n = tid + i * 256;
        const float4* l4 = (const float4*)(L + (size_t)n * HH);
        float4 v0 = l4[0], v1 = l4[1], v2 = l4[2], v3 = l4[3];
        m[0] = fmaxf(m[0], v0.x); m[1] = fmaxf(m[1], v0.y); m[2] = fmaxf(m[2], v0.z); m[3] = fmaxf(m[3], v0.w);
        m[4] = fmaxf(m[4], v1.x); m[5] = fmaxf(m[5], v1.y); m[6] = fmaxf(m[6], v1.z); m[7] = fmaxf(m[7], v1.w);
        m[8] = fmaxf(m[8], v2.x); m[9] = fmaxf(m[9], v2.y); m[10] = fmaxf(m[10], v2.z); m[11] = fmaxf(m[11], v2.w);
        m[12] = fmaxf(m[12], v3.x); m[13] = fmaxf(m[13], v3.y); m[14] = fmaxf(m[14], v3.z); m[15] = fmaxf(m[15], v3.w);
    }
#pragma unroll
    for (int h = 0; h < 16; ++h) red[tid][h] = m[h];
    __syncthreads();
    for (int st = 128; st > 0; st >>= 1) {
        if (tid < st) {
#pragma unroll
            for (int h = 0; h < 16; ++h) red[tid][h] = fmaxf(red[tid][h], red[tid + st][h]);
        }
        __syncthreads();
    }
#pragma unroll
    for (int h = 0; h < 16; ++h) m[h] = red[0][h];
    if (tid < 16) g_smax[((size_t)b * NSTRIP + s) * HH + tid] = red[0][tid];
    __syncthreads();

    float sm[16];
#pragma unroll
    for (int h = 0; h < 16; ++h) sm[h] = 0.f;
#pragma unroll
    for (int i = 0; i < 2; ++i) {
        int n = tid + i * 256;
        const float* l = L + (size_t)n * HH;
        float4* a4 = (float4*)(A + (size_t)n * HH);
        float r[16];
#pragma unroll
        for (int h = 0; h < 16; ++h) { r[h] = __expf(l[h] - m[h]); sm[h] += r[h]; }
        a4[0] = make_float4(r[0], r[1], r[2], r[3]);
        a4[1] = make_float4(r[4], r[5], r[6], r[7]);
        a4[2] = make_float4(r[8], r[9], r[10], r[11]);
        a4[3] = make_float4(r[12], r[13], r[14], r[15]);
    }
#pragma unroll
    for (int h = 0; h < 16; ++h) red[tid][h] = sm[h];
    __syncthreads();
    for (int st = 128; st > 0; st >>= 1) {
        if (tid < st) {
#pragma unroll
            for (int h = 0; h < 16; ++h) red[tid][h] += red[tid + st][h];
        }
        __syncthreads();
    }
    if (tid < 16) g_ssum[((size_t)b * NSTRIP + s) * HH + tid] = red[0][tid];
}

// ---------------- kernel Cb: combine strip stats -> per-strip rescale factor
__global__ void kCb() {
    int b = blockIdx.x, h = threadIdx.x;  // 16 threads
    float M = -1e30f;
#pragma unroll
    for (int s = 0; s < NSTRIP; ++s)
        M = fmaxf(M, g_smax[((size_t)b * NSTRIP + s) * HH + h]);
    float S = 0.f;
#pragma unroll
    for (int s = 0; s < NSTRIP; ++s)
        S += g_ssum[((size_t)b * NSTRIP + s) * HH + h] *
             __expf(g_smax[((size_t)b * NSTRIP + s) * HH + h] - M);
    float invS = 1.f / S;
#pragma unroll
    for (int s = 0; s < NSTRIP; ++s)
        g_f[((size_t)b * NSTRIP + s) * HH + h] =
            __expf(g_smax[((size_t)b * NSTRIP + s) * HH + h] - M) * invS;
}

// ---------------- kernel D1: split-K partials
// grid (4 c-tiles, 8 n-chunks, B) = 1024 CTAs, block 256.
// part[b][ch][h][c] = sum_{n in chunk} (exp[n][h]*f[b][ch][h]) * x[b][n][c]
__global__ void kD1(const float* __restrict__ x) {
    int ct = blockIdx.x, ch = blockIdx.y, b = blockIdx.z, tid = threadIdx.x;
    int c0 = ct * 256 + tid;
    __shared__ float4 ats[512 * 4];  // scaled attn tile [n][4 x float4] = 32KB

    const float4* asrc = (const float4*)(g_attnT + ((size_t)b * NN + ch * STRIP) * HH);
    const float4* f4p = (const float4*)(g_f + ((size_t)b * NSTRIP + ch) * HH);
    float4 fv0 = f4p[0], fv1 = f4p[1], fv2 = f4p[2], fv3 = f4p[3];
#pragma unroll
    for (int i = 0; i < 8; ++i) {
        int idx = tid + i * 256;
        int j = idx & 3;
        float4 v = asrc[idx];
        float4 fj = (j == 0) ? fv0 : (j == 1) ? fv1 : (j == 2) ? fv2 : fv3;
        v.x *= fj.x; v.y *= fj.y; v.z *= fj.z; v.w *= fj.w;
        ats[idx] = v;
    }
    __syncthreads();

    u64 acc[8];
#pragma unroll
    for (int j = 0; j < 8; ++j) acc[j] = 0ull;

    const u64* au = (const u64*)ats;
    const float* xb = x + ((size_t)b * NN + ch * STRIP) * CC + c0;
#pragma unroll 8
    for (int n = 0; n < STRIP; ++n) {
        u64 xd = dup2(xb[(size_t)n * CC]);
        fma2(acc[0], xd, au[n * 8 + 0]);
        fma2(acc[1], xd, au[n * 8 + 1]);
        fma2(acc[2], xd, au[n * 8 + 2]);
        fma2(acc[3], xd, au[n * 8 + 3]);
        fma2(acc[4], xd, au[n * 8 + 4]);
        fma2(acc[5], xd, au[n * 8 + 5]);
        fma2(acc[6], xd, au[n * 8 + 6]);
        fma2(acc[7], xd, au[n * 8 + 7]);
    }
    size_t base = ((size_t)b * NSTRIP + ch) * HH * CC;
#pragma unroll
    for (int j = 0; j < 8; ++j) {
        float2 v = *reinterpret_cast<float2*>(&acc[j]);
        g_part[base + (size_t)(2 * j + 0) * CC + c0] = v.x;
        g_part[base + (size_t)(2 * j + 1) * CC + c0] = v.y;
    }
}

// ---------------- kernel D2: reduce partials over chunks -> g_s
__global__ void kD2() {
    int b = blockIdx.y, tid = threadIdx.x;
    int c0 = blockIdx.x * 256 + tid;
#pragma unroll
    for (int h = 0; h < 16; ++h) {
        float s = 0.f;
#pragma unroll
        for (int ch = 0; ch < NSTRIP; ++ch)
            s += g_part[(((size_t)b * NSTRIP + ch) * HH + h) * CC + c0];
        g_s[((size_t)b * HH + h) * CC + c0] = s;
    }
}

// ---------------- kernel E: o[j] = sum_c s[b][j/16][c]*Wv[c][j]; out = o@Wp + bp
__global__ void kE(const float* __restrict__ Wv, const float* __restrict__ Wp,
                   const float* __restrict__ bp, float* __restrict__ out) {
    int b = blockIdx.x, tid = threadIdx.x;
    __shared__ float o_s[CR];
    const float* sb = g_s + ((size_t)b * HH + (tid >> 4)) * CC;
    float a = 0.f;
    for (int c = 0; c < CC; ++c) a += sb[c] * Wv[(size_t)c * CR + tid];
    o_s[tid] = a;
    __syncthreads();
#pragma unroll
    for (int i = 0; i < 4; ++i) {
        int j = tid + i * 256;
        float r = bp[j];
        for (int c2 = 0; c2 < CR; ++c2) r += o_s[c2] * Wp[(size_t)c2 * CC + j];
        out[(size_t)b * CC + j] = r;
    }
}

extern "C" void kernel_launch(void* const* d_in, const int* in_sizes, int n_in,
                              void* d_out, int out_size) {
    const float* x  = (const float*)d_in[0];
    const float* Wq = (const float*)d_in[1];
    const float* Wk = (const float*)d_in[2];
    const float* Wv = (const float*)d_in[3];
    const float* Wp = (const float*)d_in[4];
    const float* bp = (const float*)d_in[5];
    float* out = (float*)d_out;

    kA<<<BB, 256>>>(x, Wq, Wk);
    kB<<<dim3(NN / 256, BB), 256>>>(x);
    kCa<<<dim3(NSTRIP, BB), 256>>>();
    kCb<<<BB, HH>>>();
    kD1<<<dim3(4, NSTRIP, BB), 256>>>(x);
    kD2<<<dim3(4, BB), 256>>>();
    kE<<<BB, 256>>>(Wv, Wp, bp, out);
}